// round 11
// baseline (speedup 1.0000x reference)
#include <cuda_runtime.h>
#include <cuda_fp16.h>
#include <math.h>

#define HH 1024
#define WW 1024
#define BBATCH 8
#define PLANE (HH*WW)          // 1<<20
#define NPIX (BBATCH*PLANE)    // 8<<20

// fp16 intermediates: pooling is exact selection on quantized values.
// __align__(16): these are accessed with uint4 (16B) vector loads.
__device__ __align__(16) __half g_E[NPIX];   // edge_soft
__device__ __align__(16) __half g_A[NPIX];   // ping
__device__ __align__(16) __half g_B2[NPIX];  // pong
__device__ float  g_acc[3];    // mask_sum, chroma_sum, hue_sum

__device__ __forceinline__ float4 ld4f(const float* p){ return *reinterpret_cast<const float4*>(p); }

template<bool M>
__device__ __forceinline__ float rop(float a, float b){ return M ? fmaxf(a,b) : fminf(a,b); }

// 8 halves -> 8 floats
__device__ __forceinline__ void h8f(const uint4 v, float* f)
{
    float2 p;
    p = __half22float2(*reinterpret_cast<const __half2*>(&v.x)); f[0]=p.x; f[1]=p.y;
    p = __half22float2(*reinterpret_cast<const __half2*>(&v.y)); f[2]=p.x; f[3]=p.y;
    p = __half22float2(*reinterpret_cast<const __half2*>(&v.z)); f[4]=p.x; f[5]=p.y;
    p = __half22float2(*reinterpret_cast<const __half2*>(&v.w)); f[6]=p.x; f[7]=p.y;
}

// ---------------------------------------------------------------------------
// Pass 1: Sobel edge (zero-padded), |gx|+|gy|, max over channels, clip -> half
// ---------------------------------------------------------------------------
#define ET 8

__device__ __forceinline__ void load_row6(const float* p, int x0, float* r)
{
    r[0] = (x0 > 0) ? p[x0-1] : 0.f;
    float4 v = ld4f(p + x0); r[1]=v.x; r[2]=v.y; r[3]=v.z; r[4]=v.w;
    r[5] = (x0+4 < WW) ? p[x0+4] : 0.f;
}

__device__ __forceinline__ void zero_row6(float* r)
{
    #pragma unroll
    for (int i=0;i<6;i++) r[i]=0.f;
}

__global__ void __launch_bounds__(256) edge_kernel(const float* __restrict__ t)
{
    int x0  = threadIdx.x << 2;
    int grp = blockIdx.x;
    int b   = grp / (HH/ET);
    int y0  = (grp % (HH/ET)) * ET;

    float g[ET][4];
    #pragma unroll
    for (int k=0;k<ET;k++){ g[k][0]=0.f; g[k][1]=0.f; g[k][2]=0.f; g[k][3]=0.f; }

    #pragma unroll
    for (int c = 0; c < 3; c++) {
        const float* p = t + (size_t)b*3*PLANE + (size_t)c*PLANE;
        float row[3][6];
        if (y0 > 0) load_row6(p + (size_t)(y0-1)*WW, x0, row[0]);
        else        zero_row6(row[0]);
        load_row6(p + (size_t)y0*WW, x0, row[1]);

        #pragma unroll
        for (int k = 0; k < ET; k++) {
            int ynext = y0 + k + 1;
            float* nr = row[(k+2)%3];
            if (ynext <= HH-1) load_row6(p + (size_t)ynext*WW, x0, nr);
            else               zero_row6(nr);

            const float* a  = row[ k   %3];
            const float* bm = row[(k+1)%3];
            const float* cm = row[(k+2)%3];

            float s[6], d[6];
            #pragma unroll
            for (int i=0;i<6;i++){ s[i] = fmaf(2.f, bm[i], a[i]+cm[i]); d[i] = cm[i]-a[i]; }
            #pragma unroll
            for (int j=0;j<4;j++){
                float gx = s[j+2] - s[j];
                float gy = fmaf(2.f, d[j+1], d[j]+d[j+2]);
                g[k][j] = fmaxf(g[k][j], fabsf(gx) + fabsf(gy));
            }
        }
    }

    __half* obase = g_E + (size_t)b*PLANE + x0;
    #pragma unroll
    for (int k=0;k<ET;k++){
        __half2 lo = __floats2half2_rn(fminf(g[k][0]*2.f,1.f), fminf(g[k][1]*2.f,1.f));
        __half2 hi = __floats2half2_rn(fminf(g[k][2]*2.f,1.f), fminf(g[k][3]*2.f,1.f));
        uint2 v; v.x = *reinterpret_cast<unsigned*>(&lo); v.y = *reinterpret_cast<unsigned*>(&hi);
        *reinterpret_cast<uint2*>(obase + (size_t)(y0+k)*WW) = v;
    }
}

// ---------------------------------------------------------------------------
// Horizontal 11-tap pool (half), 8 outputs/thread: 3 x uint4 (24 halves,
// cols c0-8..c0+15), fp32 log-tree, out[j] = reduce a[j+3..j+13].
// ---------------------------------------------------------------------------
template<bool M>
__device__ __forceinline__ void hpool8_body(const __half* __restrict__ in, __half* __restrict__ out)
{
    int t   = threadIdx.x;
    int row = blockIdx.x * 2 + (t >> 7);
    int c0  = (t & 127) << 3;
    const __half* p = in + (size_t)row*WW;

    float a[24];
    if (c0 >= 8 && c0 <= WW-16) {
        uint4 v0 = *reinterpret_cast<const uint4*>(p + c0 - 8);
        uint4 v1 = *reinterpret_cast<const uint4*>(p + c0);
        uint4 v2 = *reinterpret_cast<const uint4*>(p + c0 + 8);
        h8f(v0, a); h8f(v1, a+8); h8f(v2, a+16);
    } else {
        #pragma unroll
        for (int i = 0; i < 24; i++) {
            int xx = c0 - 8 + i; xx = xx < 0 ? 0 : (xx > WW-1 ? WW-1 : xx);
            a[i] = __half2float(p[xx]);
        }
    }

    float m2[16], m4[12], m8[8];
    #pragma unroll
    for (int i = 0; i < 16; i++) m2[i] = rop<M>(a[i+3],  a[i+4]);    // m2[i] = a[i+3..i+4]
    #pragma unroll
    for (int i = 0; i < 12; i++) m4[i] = rop<M>(m2[i], m2[i+2]);     // a[i+3..i+6]
    #pragma unroll
    for (int i = 0; i <  8; i++) m8[i] = rop<M>(m4[i], m4[i+4]);     // a[i+3..i+10]

    float r[8];
    #pragma unroll
    for (int j = 0; j < 8; j++)
        r[j] = rop<M>(m8[j], rop<M>(m2[j+8], a[j+13]));              // a[j+3..j+13]

    uint4 o;
    __half2 h0 = __floats2half2_rn(r[0], r[1]);
    __half2 h1 = __floats2half2_rn(r[2], r[3]);
    __half2 h2 = __floats2half2_rn(r[4], r[5]);
    __half2 h3 = __floats2half2_rn(r[6], r[7]);
    o.x = *reinterpret_cast<unsigned*>(&h0);
    o.y = *reinterpret_cast<unsigned*>(&h1);
    o.z = *reinterpret_cast<unsigned*>(&h2);
    o.w = *reinterpret_cast<unsigned*>(&h3);
    *reinterpret_cast<uint4*>(out + (size_t)row*WW + c0) = o;
}

__global__ void __launch_bounds__(256) k_hmax11(){ hpool8_body<true >(g_E,  g_A); }
__global__ void __launch_bounds__(256) k_hmin11(){ hpool8_body<false>(g_B2, g_A); }

// ---------------------------------------------------------------------------
// Vertical 11-tap pool (half), 8 output rows/thread, 4 cols: 18 x 8B loads
// (MLP=18), native half2 log-tree.
// ---------------------------------------------------------------------------
struct H4 { __half2 x, y; };

__device__ __forceinline__ H4 ldh4(const __half* p)
{
    uint2 v = *reinterpret_cast<const uint2*>(p);
    H4 r;
    r.x = *reinterpret_cast<__half2*>(&v.x);
    r.y = *reinterpret_cast<__half2*>(&v.y);
    return r;
}

__device__ __forceinline__ void sth4(__half* p, H4 h)
{
    uint2 v;
    v.x = *reinterpret_cast<unsigned*>(&h.x);
    v.y = *reinterpret_cast<unsigned*>(&h.y);
    *reinterpret_cast<uint2*>(p) = v;
}

template<bool M>
__device__ __forceinline__ H4 roph4(H4 a, H4 b)
{
    H4 r;
    if (M) { r.x = __hmax2(a.x, b.x); r.y = __hmax2(a.y, b.y); }
    else   { r.x = __hmin2(a.x, b.x); r.y = __hmin2(a.y, b.y); }
    return r;
}

template<bool M>
__device__ __forceinline__ void vpool8_body(const __half* __restrict__ in, __half* __restrict__ out)
{
    int t   = threadIdx.x;
    int x0  = t << 2;                  // 256 threads x 4 cols = full row
    int grp = blockIdx.x;
    int b   = grp >> 7;                // 128 groups per batch
    int y0  = (grp & 127) << 3;        // 8 rows per group
    const __half* base  = in  + (size_t)b*PLANE + x0;
    __half*       obase = out + (size_t)b*PLANE + x0;

    H4 a[18];
    #pragma unroll
    for (int i = 0; i < 18; i++) {
        int yy = y0 - 5 + i; yy = yy < 0 ? 0 : (yy > HH-1 ? HH-1 : yy);
        a[i] = ldh4(base + (size_t)yy*WW);
    }

    H4 m2[16], m4[12], m8[8];
    #pragma unroll
    for (int i = 0; i < 16; i++) m2[i] = roph4<M>(a[i],  a[i+1]);
    #pragma unroll
    for (int i = 0; i < 12; i++) m4[i] = roph4<M>(m2[i], m2[i+2]);
    #pragma unroll
    for (int i = 0; i <  8; i++) m8[i] = roph4<M>(m4[i], m4[i+4]);

    #pragma unroll
    for (int j = 0; j < 8; j++) {
        H4 o = roph4<M>(m8[j], roph4<M>(m2[j+8], a[j+10]));
        sth4(obase + (size_t)(y0+j)*WW, o);
    }
}

__global__ void __launch_bounds__(256) k_vmax11(){ vpool8_body<true >(g_A, g_B2); }
__global__ void __launch_bounds__(256) k_vmin11(){ vpool8_body<false>(g_A, g_B2); }

// ---------------------------------------------------------------------------
// Fused final kernel: mask = relu(closed-edge) -> 5x5 max -> masked OKLab loss.
// 8 cols/thread; ring of 5 h5-pooled rows; atomics only.
// ---------------------------------------------------------------------------
__device__ __forceinline__ void maskrow13(const __half* __restrict__ pc,
                                          const __half* __restrict__ pe,
                                          int c0, float* m)   // m[0..12] = cols c0-2 .. c0+10
{
    if (c0 >= 8 && c0 <= WW-16) {
        uint4 C0 = *reinterpret_cast<const uint4*>(pc + c0 - 8);
        uint4 C1 = *reinterpret_cast<const uint4*>(pc + c0);
        uint4 C2 = *reinterpret_cast<const uint4*>(pc + c0 + 8);
        uint4 E0 = *reinterpret_cast<const uint4*>(pe + c0 - 8);
        uint4 E1 = *reinterpret_cast<const uint4*>(pe + c0);
        uint4 E2 = *reinterpret_cast<const uint4*>(pe + c0 + 8);
        float2 c67 = __half22float2(*reinterpret_cast<const __half2*>(&C0.w));
        float2 e67 = __half22float2(*reinterpret_cast<const __half2*>(&E0.w));
        m[0] = fmaxf(c67.x - e67.x, 0.f);
        m[1] = fmaxf(c67.y - e67.y, 0.f);
        float c8[8], e8[8];
        h8f(C1, c8); h8f(E1, e8);
        #pragma unroll
        for (int i = 0; i < 8; i++) m[2+i] = fmaxf(c8[i] - e8[i], 0.f);
        float2 cA = __half22float2(*reinterpret_cast<const __half2*>(&C2.x));
        float2 eA = __half22float2(*reinterpret_cast<const __half2*>(&E2.x));
        float2 cB = __half22float2(*reinterpret_cast<const __half2*>(&C2.y));
        float2 eB = __half22float2(*reinterpret_cast<const __half2*>(&E2.y));
        m[10] = fmaxf(cA.x - eA.x, 0.f);
        m[11] = fmaxf(cA.y - eA.y, 0.f);
        m[12] = fmaxf(cB.x - eB.x, 0.f);
    } else {
        #pragma unroll
        for (int i = 0; i < 13; i++) {
            int xx = c0 - 2 + i; xx = xx < 0 ? 0 : (xx > WW-1 ? WW-1 : xx);
            m[i] = fmaxf(__half2float(pc[xx]) - __half2float(pe[xx]), 0.f);
        }
    }
}

// h5 over m[0..12]: out[j] = max m[j..j+4], j=0..7
__device__ __forceinline__ void h5tree(const float* m, float* o)
{
    float t2[12], t4[9];
    #pragma unroll
    for (int i = 0; i < 12; i++) t2[i] = fmaxf(m[i], m[i+1]);
    #pragma unroll
    for (int i = 0; i <  9; i++) t4[i] = fmaxf(t2[i], t2[i+2]);
    #pragma unroll
    for (int j = 0; j <  8; j++) o[j]  = fmaxf(t4[j], m[j+4]);
}

__device__ __forceinline__ float s2l(float x)
{
    x = fminf(fmaxf(x, 0.f), 1.f);
    return (x <= 0.04045f) ? x * (1.f/12.92f)
                           : __powf((x + 0.055f) * (1.f/1.055f), 2.4f);
}

__device__ __forceinline__ void oklab_ab(float r, float g, float bl, float& A, float& Bc)
{
    float lr = s2l(r), lg = s2l(g), lb = s2l(bl);
    float l = 0.4122214708f*lr + 0.5363325363f*lg + 0.0514459929f*lb;
    float m = 0.2119034982f*lr + 0.6806995451f*lg + 0.1073969566f*lb;
    float s = 0.0883024619f*lr + 0.2817188376f*lg + 0.6299787005f*lb;
    l = cbrtf(fmaxf(l, 1e-10f));
    m = cbrtf(fmaxf(m, 1e-10f));
    s = cbrtf(fmaxf(s, 1e-10f));
    A  = 1.9779984951f*l - 2.428592205f*m + 0.4505937099f*s;
    Bc = 0.0259040371f*l + 0.7827717662f*m - 0.808675766f*s;
}

__global__ void __launch_bounds__(256) k_maskloss(const float* __restrict__ pred,
                                                  const float* __restrict__ tgt)
{
    int t    = threadIdx.x;
    int c0   = (t & 127) << 3;
    int rg   = t >> 7;                   // 0..1
    int grp  = blockIdx.x;               // 512 blocks
    int b    = grp >> 6;                 // 64 groups per batch
    int y0   = ((grp & 63) << 4) + rg*8; // 16 rows per block, 8 per half
    const __half* cb = g_B2 + (size_t)b*PLANE;   // closed
    const __half* eb = g_E  + (size_t)b*PLANE;   // edge

    float msum = 0.f, chroma = 0.f, hue = 0.f;

    float ring[5][8];
    #pragma unroll
    for (int i = 0; i < 4; i++) {
        int yy = y0 - 2 + i; yy = yy < 0 ? 0 : yy;
        float m[13];
        maskrow13(cb + (size_t)yy*WW, eb + (size_t)yy*WW, c0, m);
        h5tree(m, ring[i]);
    }
    #pragma unroll
    for (int k = 0; k < 8; k++) {
        int yy = y0 + k + 2; yy = yy > HH-1 ? HH-1 : yy;
        {
            float m[13];
            maskrow13(cb + (size_t)yy*WW, eb + (size_t)yy*WW, c0, m);
            h5tree(m, ring[(4+k)%5]);
        }
        float o[8];
        #pragma unroll
        for (int j = 0; j < 8; j++) {
            float v = ring[0][j];
            v = fmaxf(v, ring[1][j]); v = fmaxf(v, ring[2][j]);
            v = fmaxf(v, ring[3][j]); v = fmaxf(v, ring[4][j]);
            o[j] = v;
        }
        float rowsum = 0.f;
        #pragma unroll
        for (int j = 0; j < 8; j++) rowsum += o[j];
        msum += rowsum;
        if (rowsum > 0.f) {
            size_t base = (size_t)b*3*PLANE + (size_t)(y0+k)*WW + c0;
            #pragma unroll 1
            for (int j = 0; j < 8; j++) {
                float m = o[j];
                if (m > 0.f) {
                    float pa,pb,ta,tb;
                    oklab_ab(pred[base+j], pred[base+j+PLANE], pred[base+j+2*PLANE], pa, pb);
                    oklab_ab(tgt [base+j], tgt [base+j+PLANE], tgt [base+j+2*PLANE], ta, tb);
                    float Cp = sqrtf(fmaf(pa,pa, pb*pb) + 1e-12f);
                    float Cg = sqrtf(fmaf(ta,ta, tb*tb) + 1e-12f);
                    chroma += fabsf(Cp - Cg) * m;
                    float cosd = (pa*ta + pb*tb) / (Cp*Cg + 1e-12f);
                    cosd = fminf(fmaxf(cosd, -1.f), 1.f);
                    hue += fmaxf(Cg, 0.01f) * (1.f - cosd) * m;
                }
            }
        }
    }

    #pragma unroll
    for (int o2=16; o2; o2>>=1){
        msum   += __shfl_xor_sync(0xffffffffu, msum,   o2);
        chroma += __shfl_xor_sync(0xffffffffu, chroma, o2);
        hue    += __shfl_xor_sync(0xffffffffu, hue,    o2);
    }
    __shared__ float sm[3][8];
    int w = t >> 5, lane = t & 31;
    if (lane == 0){ sm[0][w]=msum; sm[1][w]=chroma; sm[2][w]=hue; }
    __syncthreads();
    if (t == 0){
        float a=0.f, c=0.f, h=0.f;
        #pragma unroll
        for (int i=0;i<8;i++){ a+=sm[0][i]; c+=sm[1][i]; h+=sm[2][i]; }
        atomicAdd(&g_acc[0], a);
        atomicAdd(&g_acc[1], c);
        atomicAdd(&g_acc[2], h);
    }
}

__global__ void k_zero(){ if (threadIdx.x < 3) g_acc[threadIdx.x] = 0.f; }

__global__ void k_fin(float* out)
{
    float ms = fmaxf(g_acc[0], 1.f);
    out[0] = g_acc[1]/ms + 2.f*(g_acc[2]/ms);
}

// ---------------------------------------------------------------------------
extern "C" void kernel_launch(void* const* d_in, const int* in_sizes, int n_in,
                              void* d_out, int out_size)
{
    const float* pred = (const float*)d_in[0];
    const float* tgt  = (const float*)d_in[1];
    float* out = (float*)d_out;

    const int egrid = BBATCH*HH/ET;        // 1024
    const int hgrid = BBATCH*HH/2;         // 4096 (2 rows/block)
    const int vgrid = BBATCH*(HH/8);       // 1024 (8 rows x 1024 cols/block)
    const int mgrid = BBATCH*(HH/16);      // 512  (16 rows x 1024 cols/block)
    dim3 blk(256);

    k_zero     <<<1, 32>>>();
    edge_kernel<<<egrid, blk>>>(tgt);       // target -> g_E (half)
    k_hmax11   <<<hgrid, blk>>>();          // g_E  -> g_A
    k_vmax11   <<<vgrid, blk>>>();          // g_A  -> g_B2 (dilated)
    k_hmin11   <<<hgrid, blk>>>();          // g_B2 -> g_A
    k_vmin11   <<<vgrid, blk>>>();          // g_A  -> g_B2 (closed)
    k_maskloss <<<mgrid, blk>>>(pred, tgt); // -> g_acc
    k_fin      <<<1, 1>>>(out);
}

// round 14
// speedup vs baseline: 1.2244x; 1.2244x over previous
#include <cuda_runtime.h>
#include <cuda_fp16.h>
#include <math.h>

#define HH 1024
#define WW 1024
#define BBATCH 8
#define PLANE (HH*WW)          // 1<<20
#define NPIX (BBATCH*PLANE)    // 8<<20

// fp16 intermediates: pooling is exact selection on quantized values.
__device__ __align__(16) __half g_E[NPIX];   // edge_soft
__device__ __align__(16) __half g_A[NPIX];   // ping
__device__ __align__(16) __half g_B2[NPIX];  // pong
__device__ float  g_acc[3];    // mask_sum, chroma_sum, hue_sum

__device__ __forceinline__ float4 ld4f(const float* p){ return *reinterpret_cast<const float4*>(p); }

template<bool M>
__device__ __forceinline__ float rop(float a, float b){ return M ? fmaxf(a,b) : fminf(a,b); }

__device__ __forceinline__ float2 h2f(unsigned u){ return __half22float2(*reinterpret_cast<const __half2*>(&u)); }

// ---------------------------------------------------------------------------
// Pass 1: Sobel edge (zero-padded), |gx|+|gy|, max over channels, clip -> half
// ---------------------------------------------------------------------------
#define ET 8

__device__ __forceinline__ void load_row6(const float* p, int x0, float* r)
{
    r[0] = (x0 > 0) ? p[x0-1] : 0.f;
    float4 v = ld4f(p + x0); r[1]=v.x; r[2]=v.y; r[3]=v.z; r[4]=v.w;
    r[5] = (x0+4 < WW) ? p[x0+4] : 0.f;
}

__device__ __forceinline__ void zero_row6(float* r)
{
    #pragma unroll
    for (int i=0;i<6;i++) r[i]=0.f;
}

__global__ void __launch_bounds__(256) edge_kernel(const float* __restrict__ t)
{
    int x0  = threadIdx.x << 2;
    int grp = blockIdx.x;
    int b   = grp / (HH/ET);
    int y0  = (grp % (HH/ET)) * ET;

    float g[ET][4];
    #pragma unroll
    for (int k=0;k<ET;k++){ g[k][0]=0.f; g[k][1]=0.f; g[k][2]=0.f; g[k][3]=0.f; }

    #pragma unroll
    for (int c = 0; c < 3; c++) {
        const float* p = t + (size_t)b*3*PLANE + (size_t)c*PLANE;
        float row[3][6];
        if (y0 > 0) load_row6(p + (size_t)(y0-1)*WW, x0, row[0]);
        else        zero_row6(row[0]);
        load_row6(p + (size_t)y0*WW, x0, row[1]);

        #pragma unroll
        for (int k = 0; k < ET; k++) {
            int ynext = y0 + k + 1;
            float* nr = row[(k+2)%3];
            if (ynext <= HH-1) load_row6(p + (size_t)ynext*WW, x0, nr);
            else               zero_row6(nr);

            const float* a  = row[ k   %3];
            const float* bm = row[(k+1)%3];
            const float* cm = row[(k+2)%3];

            float s[6], d[6];
            #pragma unroll
            for (int i=0;i<6;i++){ s[i] = fmaf(2.f, bm[i], a[i]+cm[i]); d[i] = cm[i]-a[i]; }
            #pragma unroll
            for (int j=0;j<4;j++){
                float gx = s[j+2] - s[j];
                float gy = fmaf(2.f, d[j+1], d[j]+d[j+2]);
                g[k][j] = fmaxf(g[k][j], fabsf(gx) + fabsf(gy));
            }
        }
    }

    __half* obase = g_E + (size_t)b*PLANE + x0;
    #pragma unroll
    for (int k=0;k<ET;k++){
        __half2 lo = __floats2half2_rn(fminf(g[k][0]*2.f,1.f), fminf(g[k][1]*2.f,1.f));
        __half2 hi = __floats2half2_rn(fminf(g[k][2]*2.f,1.f), fminf(g[k][3]*2.f,1.f));
        uint2 v; v.x = *reinterpret_cast<unsigned*>(&lo); v.y = *reinterpret_cast<unsigned*>(&hi);
        *reinterpret_cast<uint2*>(obase + (size_t)(y0+k)*WW) = v;
    }
}

// ---------------------------------------------------------------------------
// Horizontal 11-tap pool (half), shared-prefix shape, alignment-safe loads:
// 4 outputs/thread, one row/block. a[0..13] = cols x0-5 .. x0+8.
// x0 is a multiple of 4 halves (8 bytes): u32 loads need 4B-multiple offsets
// (x0-6, x0+8 are even halves -> 4B aligned), uint2 loads 8B (x0-4, x0, x0+4
// are multiples of 4 halves -> 8B aligned). No 16B accesses.
// ---------------------------------------------------------------------------
template<bool M>
__device__ __forceinline__ void hpool4_body(const __half* __restrict__ in, __half* __restrict__ out)
{
    int row = blockIdx.x;
    int x0  = threadIdx.x << 2;
    const __half* p = in + (size_t)row*WW;

    float a[14];
    if (x0 >= 8 && x0 <= WW-12) {
        unsigned u0 = *reinterpret_cast<const unsigned*>(p + x0 - 6);  // x0-6, x0-5
        uint2 v0 = *reinterpret_cast<const uint2*>(p + x0 - 4);        // x0-4..x0-1
        uint2 v1 = *reinterpret_cast<const uint2*>(p + x0);            // x0..x0+3
        uint2 v2 = *reinterpret_cast<const uint2*>(p + x0 + 4);        // x0+4..x0+7
        unsigned u1 = *reinterpret_cast<const unsigned*>(p + x0 + 8);  // x0+8, x0+9
        float2 q;
        q = h2f(u0);   a[0] = q.y;                 // x0-5
        q = h2f(v0.x); a[1] = q.x; a[2] = q.y;     // x0-4, x0-3
        q = h2f(v0.y); a[3] = q.x; a[4] = q.y;     // x0-2, x0-1
        q = h2f(v1.x); a[5] = q.x; a[6] = q.y;
        q = h2f(v1.y); a[7] = q.x; a[8] = q.y;
        q = h2f(v2.x); a[9] = q.x; a[10]= q.y;
        q = h2f(v2.y); a[11]= q.x; a[12]= q.y;
        q = h2f(u1);   a[13]= q.x;                 // x0+8
    } else {
        #pragma unroll
        for (int i=0;i<14;i++){
            int xx = x0-5+i; xx = xx < 0 ? 0 : (xx > WW-1 ? WW-1 : xx);
            a[i] = __half2float(p[xx]);
        }
    }
    float C = a[3];
    #pragma unroll
    for (int i=4;i<=10;i++) C = rop<M>(C, a[i]);
    float t12 = rop<M>(a[1],  a[2]);
    float t23 = rop<M>(a[11], a[12]);
    float o0 = rop<M>(C, rop<M>(a[0], t12));
    float o1 = rop<M>(C, rop<M>(t12,  a[11]));
    float o2 = rop<M>(rop<M>(C, a[2]),  t23);
    float o3 = rop<M>(rop<M>(C, a[13]), t23);

    __half2 lo = __floats2half2_rn(o0, o1);
    __half2 hi = __floats2half2_rn(o2, o3);
    uint2 v; v.x = *reinterpret_cast<unsigned*>(&lo); v.y = *reinterpret_cast<unsigned*>(&hi);
    *reinterpret_cast<uint2*>(out + (size_t)row*WW + x0) = v;
}

__global__ void __launch_bounds__(256) k_hmax11(){ hpool4_body<true >(g_E,  g_A); }
__global__ void __launch_bounds__(256) k_hmin11(){ hpool4_body<false>(g_B2, g_A); }

// ---------------------------------------------------------------------------
// Vertical 11-tap pool (half), 8 output rows/thread, 4 cols: 18 x 8B loads
// (MLP=18), native half2 log-tree.  [measured 9.15us]
// ---------------------------------------------------------------------------
struct H4 { __half2 x, y; };

__device__ __forceinline__ H4 ldh4(const __half* p)
{
    uint2 v = *reinterpret_cast<const uint2*>(p);
    H4 r;
    r.x = *reinterpret_cast<__half2*>(&v.x);
    r.y = *reinterpret_cast<__half2*>(&v.y);
    return r;
}

__device__ __forceinline__ void sth4(__half* p, H4 h)
{
    uint2 v;
    v.x = *reinterpret_cast<unsigned*>(&h.x);
    v.y = *reinterpret_cast<unsigned*>(&h.y);
    *reinterpret_cast<uint2*>(p) = v;
}

template<bool M>
__device__ __forceinline__ H4 roph4(H4 a, H4 b)
{
    H4 r;
    if (M) { r.x = __hmax2(a.x, b.x); r.y = __hmax2(a.y, b.y); }
    else   { r.x = __hmin2(a.x, b.x); r.y = __hmin2(a.y, b.y); }
    return r;
}

template<bool M>
__device__ __forceinline__ void vpool8_body(const __half* __restrict__ in, __half* __restrict__ out)
{
    int t   = threadIdx.x;
    int x0  = t << 2;                  // 256 threads x 4 cols = full row
    int grp = blockIdx.x;
    int b   = grp >> 7;                // 128 groups per batch
    int y0  = (grp & 127) << 3;        // 8 rows per group
    const __half* base  = in  + (size_t)b*PLANE + x0;
    __half*       obase = out + (size_t)b*PLANE + x0;

    H4 a[18];
    #pragma unroll
    for (int i = 0; i < 18; i++) {
        int yy = y0 - 5 + i; yy = yy < 0 ? 0 : (yy > HH-1 ? HH-1 : yy);
        a[i] = ldh4(base + (size_t)yy*WW);
    }

    H4 m2[16], m4[12], m8[8];
    #pragma unroll
    for (int i = 0; i < 16; i++) m2[i] = roph4<M>(a[i],  a[i+1]);
    #pragma unroll
    for (int i = 0; i < 12; i++) m4[i] = roph4<M>(m2[i], m2[i+2]);
    #pragma unroll
    for (int i = 0; i <  8; i++) m8[i] = roph4<M>(m4[i], m4[i+4]);

    #pragma unroll
    for (int j = 0; j < 8; j++) {
        H4 o = roph4<M>(m8[j], roph4<M>(m2[j+8], a[j+10]));
        sth4(obase + (size_t)(y0+j)*WW, o);
    }
}

__global__ void __launch_bounds__(256) k_vmax11(){ vpool8_body<true >(g_A, g_B2); }
__global__ void __launch_bounds__(256) k_vmin11(){ vpool8_body<false>(g_A, g_B2); }

// ---------------------------------------------------------------------------
// Fused final kernel (round-5 shape): mask = relu(closed-edge) -> 5x5 max ->
// masked OKLab loss. 4 cols/thread, float4 ring of 5, atomics only.
// ---------------------------------------------------------------------------
__device__ __forceinline__ float4 maskrow_h5(const __half* __restrict__ pc,
                                             const __half* __restrict__ pe, int x0)
{
    float m[8];   // positions x0-2 .. x0+5
    if (x0 >= 4 && x0 <= WW-8) {
        uint2 C0 = *reinterpret_cast<const uint2*>(pc + x0 - 4);
        uint2 C1 = *reinterpret_cast<const uint2*>(pc + x0);
        uint2 C2 = *reinterpret_cast<const uint2*>(pc + x0 + 4);
        uint2 E0 = *reinterpret_cast<const uint2*>(pe + x0 - 4);
        uint2 E1 = *reinterpret_cast<const uint2*>(pe + x0);
        uint2 E2 = *reinterpret_cast<const uint2*>(pe + x0 + 4);
        float2 c, e;
        c = h2f(C0.y); e = h2f(E0.y);
        m[0] = fmaxf(c.x - e.x, 0.f); m[1] = fmaxf(c.y - e.y, 0.f);   // x0-2, x0-1
        c = h2f(C1.x); e = h2f(E1.x);
        m[2] = fmaxf(c.x - e.x, 0.f); m[3] = fmaxf(c.y - e.y, 0.f);   // x0, x0+1
        c = h2f(C1.y); e = h2f(E1.y);
        m[4] = fmaxf(c.x - e.x, 0.f); m[5] = fmaxf(c.y - e.y, 0.f);   // x0+2, x0+3
        c = h2f(C2.x); e = h2f(E2.x);
        m[6] = fmaxf(c.x - e.x, 0.f); m[7] = fmaxf(c.y - e.y, 0.f);   // x0+4, x0+5
    } else {
        #pragma unroll
        for (int i=0;i<8;i++){
            int xx = x0-2+i; xx = xx < 0 ? 0 : (xx > WW-1 ? WW-1 : xx);
            m[i] = fmaxf(__half2float(pc[xx]) - __half2float(pe[xx]), 0.f);
        }
    }
    float C   = fmaxf(m[3], m[4]);
    float t12 = fmaxf(m[1], m[2]);
    float t56 = fmaxf(m[5], m[6]);
    float4 o;
    o.x = fmaxf(C, fmaxf(m[0], t12));
    o.y = fmaxf(C, fmaxf(t12,  m[5]));
    o.z = fmaxf(fmaxf(C, m[2]), t56);
    o.w = fmaxf(fmaxf(C, m[7]), t56);
    return o;
}

__device__ __forceinline__ float s2l(float x)
{
    x = fminf(fmaxf(x, 0.f), 1.f);
    return (x <= 0.04045f) ? x * (1.f/12.92f)
                           : __powf((x + 0.055f) * (1.f/1.055f), 2.4f);
}

__device__ __forceinline__ void oklab_ab(float r, float g, float bl, float& A, float& Bc)
{
    float lr = s2l(r), lg = s2l(g), lb = s2l(bl);
    float l = 0.4122214708f*lr + 0.5363325363f*lg + 0.0514459929f*lb;
    float m = 0.2119034982f*lr + 0.6806995451f*lg + 0.1073969566f*lb;
    float s = 0.0883024619f*lr + 0.2817188376f*lg + 0.6299787005f*lb;
    l = cbrtf(fmaxf(l, 1e-10f));
    m = cbrtf(fmaxf(m, 1e-10f));
    s = cbrtf(fmaxf(s, 1e-10f));
    A  = 1.9779984951f*l - 2.428592205f*m + 0.4505937099f*s;
    Bc = 0.0259040371f*l + 0.7827717662f*m - 0.808675766f*s;
}

#define MT 8

__global__ void __launch_bounds__(256) k_maskloss(const float* __restrict__ pred,
                                                  const float* __restrict__ tgt)
{
    int x0   = threadIdx.x << 2;
    int grp  = blockIdx.x;
    int b    = grp / (HH/MT);
    int y0   = (grp % (HH/MT)) * MT;
    const __half* cb = g_B2 + (size_t)b*PLANE;   // closed
    const __half* eb = g_E  + (size_t)b*PLANE;   // edge

    float msum = 0.f, chroma = 0.f, hue = 0.f;

    float4 r[5];
    #pragma unroll
    for (int i = 0; i < 4; i++) {
        int yy = y0 - 2 + i; yy = yy < 0 ? 0 : yy;
        r[i] = maskrow_h5(cb + (size_t)yy*WW, eb + (size_t)yy*WW, x0);
    }
    #pragma unroll
    for (int k = 0; k < MT; k++) {
        int yy = y0 + k + 2; yy = yy > HH-1 ? HH-1 : yy;
        r[(4+k) % 5] = maskrow_h5(cb + (size_t)yy*WW, eb + (size_t)yy*WW, x0);
        float4 o = r[0];
        #pragma unroll
        for (int i=1;i<5;i++){
            o.x = fmaxf(o.x, r[i].x); o.y = fmaxf(o.y, r[i].y);
            o.z = fmaxf(o.z, r[i].z); o.w = fmaxf(o.w, r[i].w);
        }
        msum += (o.x + o.y) + (o.z + o.w);
        if (o.x > 0.f || o.y > 0.f || o.z > 0.f || o.w > 0.f) {
            size_t base = (size_t)b*3*PLANE + (size_t)(y0+k)*WW + x0;
            float mv[4] = {o.x, o.y, o.z, o.w};
            #pragma unroll 1
            for (int j = 0; j < 4; j++) {
                float m = mv[j];
                if (m > 0.f) {
                    float pa,pb,ta,tb;
                    oklab_ab(pred[base+j], pred[base+j+PLANE], pred[base+j+2*PLANE], pa, pb);
                    oklab_ab(tgt [base+j], tgt [base+j+PLANE], tgt [base+j+2*PLANE], ta, tb);
                    float Cp = sqrtf(fmaf(pa,pa, pb*pb) + 1e-12f);
                    float Cg = sqrtf(fmaf(ta,ta, tb*tb) + 1e-12f);
                    chroma += fabsf(Cp - Cg) * m;
                    float cosd = (pa*ta + pb*tb) / (Cp*Cg + 1e-12f);
                    cosd = fminf(fmaxf(cosd, -1.f), 1.f);
                    hue += fmaxf(Cg, 0.01f) * (1.f - cosd) * m;
                }
            }
        }
    }

    #pragma unroll
    for (int o2=16; o2; o2>>=1){
        msum   += __shfl_xor_sync(0xffffffffu, msum,   o2);
        chroma += __shfl_xor_sync(0xffffffffu, chroma, o2);
        hue    += __shfl_xor_sync(0xffffffffu, hue,    o2);
    }
    __shared__ float sm[3][8];
    int w = threadIdx.x >> 5, lane = threadIdx.x & 31;
    if (lane == 0){ sm[0][w]=msum; sm[1][w]=chroma; sm[2][w]=hue; }
    __syncthreads();
    if (threadIdx.x == 0){
        float a=0.f, c=0.f, h=0.f;
        #pragma unroll
        for (int i=0;i<8;i++){ a+=sm[0][i]; c+=sm[1][i]; h+=sm[2][i]; }
        atomicAdd(&g_acc[0], a);
        atomicAdd(&g_acc[1], c);
        atomicAdd(&g_acc[2], h);
    }
}

__global__ void k_zero(){ if (threadIdx.x < 3) g_acc[threadIdx.x] = 0.f; }

__global__ void k_fin(float* out)
{
    float ms = fmaxf(g_acc[0], 1.f);
    out[0] = g_acc[1]/ms + 2.f*(g_acc[2]/ms);
}

// ---------------------------------------------------------------------------
extern "C" void kernel_launch(void* const* d_in, const int* in_sizes, int n_in,
                              void* d_out, int out_size)
{
    const float* pred = (const float*)d_in[0];
    const float* tgt  = (const float*)d_in[1];
    float* out = (float*)d_out;

    const int egrid = BBATCH*HH/ET;        // 1024
    const int hgrid = BBATCH*HH;           // 8192 (1 row/block)
    const int vgrid = BBATCH*(HH/8);       // 1024 (8 rows x 1024 cols/block)
    const int mgrid = BBATCH*HH/MT;        // 1024
    dim3 blk(256);

    k_zero     <<<1, 32>>>();
    edge_kernel<<<egrid, blk>>>(tgt);       // target -> g_E (half)
    k_hmax11   <<<hgrid, blk>>>();          // g_E  -> g_A
    k_vmax11   <<<vgrid, blk>>>();          // g_A  -> g_B2 (dilated)
    k_hmin11   <<<hgrid, blk>>>();          // g_B2 -> g_A
    k_vmin11   <<<vgrid, blk>>>();          // g_A  -> g_B2 (closed)
    k_maskloss <<<mgrid, blk>>>(pred, tgt); // -> g_acc
    k_fin      <<<1, 1>>>(out);
}